// round 15
// baseline (speedup 1.0000x reference)
#include <cuda_runtime.h>
#include <math.h>
#include <stdint.h>

#define IN_DIM   768
#define HID      1024
#define CLIP     512
#define NG       4
#define DS       64
#define DC       4
#define HD       64
#define DIN      2048
#define NH       32
#define CONV_DIM 2560
#define DINP     4640
#define BATCH    1024
#define EPS      1e-5f

// ---------------- scratch ----------------
__device__ float g_x[BATCH * IN_DIM];
__device__ float g_gated[BATCH * HID];
__device__ float g_zx[BATCH * DINP];
__device__ float g_yn[BATCH * DIN];
__device__ float g_outpre[BATCH * HID];
__device__ float g_outf[BATCH * HID];

__device__ __forceinline__ float sigmoidf_(float v) { return 1.0f / (1.0f + expf(-v)); }
__device__ __forceinline__ float siluf_(float v)    { return v / (1.0f + expf(-v)); }

__device__ __forceinline__ unsigned f2tf32(float x) {
    unsigned r;
    asm("cvt.rna.tf32.f32 %0, %1;" : "=r"(r) : "f"(x));
    return r;
}

__device__ __forceinline__ void cp_async16(uint32_t dst, const void* src, int src_bytes) {
    asm volatile("cp.async.cg.shared.global [%0], [%1], 16, %2;\n"
                 :: "r"(dst), "l"(src), "r"(src_bytes));
}
__device__ __forceinline__ void cp_commit() {
    asm volatile("cp.async.commit_group;\n");
}
template<int N>
__device__ __forceinline__ void cp_wait() {
    asm volatile("cp.async.wait_group %0;\n" :: "n"(N));
}

// ---------------- layernorm ----------------
__global__ void ln_kernel(const float* __restrict__ ff,
                          const float* __restrict__ w,
                          const float* __restrict__ b,
                          float* __restrict__ out) {
    int row = blockIdx.x;
    const float* in = ff + (size_t)row * IN_DIM;
    float* o = out + (size_t)row * IN_DIM;
    int tid = threadIdx.x;               // 256 threads
    float v0 = in[tid], v1 = in[tid + 256], v2 = in[tid + 512];
    float s = v0 + v1 + v2;
    float s2 = v0 * v0 + v1 * v1 + v2 * v2;
    for (int o2 = 16; o2; o2 >>= 1) {
        s  += __shfl_down_sync(0xffffffffu, s,  o2);
        s2 += __shfl_down_sync(0xffffffffu, s2, o2);
    }
    __shared__ float ss[8], ss2[8];
    int wid = tid >> 5, lid = tid & 31;
    if (lid == 0) { ss[wid] = s; ss2[wid] = s2; }
    __syncthreads();
    __shared__ float mu_s, rstd_s;
    if (tid == 0) {
        float ts = 0.f, ts2 = 0.f;
        for (int i = 0; i < 8; i++) { ts += ss[i]; ts2 += ss2[i]; }
        float mu = ts / IN_DIM;
        float var = ts2 / IN_DIM - mu * mu;
        mu_s = mu;
        rstd_s = rsqrtf(var + EPS);
    }
    __syncthreads();
    float mu = mu_s, rstd = rstd_s;
    o[tid]       = (v0 - mu) * rstd * w[tid]       + b[tid];
    o[tid + 256] = (v1 - mu) * rstd * w[tid + 256] + b[tid + 256];
    o[tid + 512] = (v2 - mu) * rstd * w[tid + 512] + b[tid + 512];
}

// ---------------- TF32 tensor-core GEMM, cp.async 3-stage pipelined ----------------
// C[M,N] = A[M,K] @ W[N,K]^T (+ bias), epilogue modes:
//   0: C = acc(+bias)   1: C = other * sigmoid(acc(+bias))   2: C = acc + other
template<int BM>
__global__ __launch_bounds__(256, 2)
void tf32_gemm(const float* __restrict__ A, const float* __restrict__ W,
               const float* __restrict__ bias, const float* __restrict__ other,
               float* __restrict__ C, int M, int N, int K, int mode)
{
    constexpr int BN = 128;
    constexpr int BK = 32;
    constexpr int MT = BM / 32;
    constexpr int PITCH = 36;
    constexpr int STAGE = (BM + BN) * PITCH;

    extern __shared__ float smem[];

    int tid  = threadIdx.x;
    int warp = tid >> 5, lane = tid & 31;
    int g    = lane >> 2, tig = lane & 3;
    int wm   = (warp >> 2) * (MT * 16);
    int wn   = (warp & 3) * 32;
    int m0   = blockIdx.y * BM;
    int n0   = blockIdx.x * BN;

    int lrow = tid >> 3;          // 0..31
    int lcol = (tid & 7) * 4;     // 0,4,...,28

    float acc[MT][4][4];
#pragma unroll
    for (int i = 0; i < MT; i++)
#pragma unroll
        for (int j = 0; j < 4; j++)
#pragma unroll
            for (int c = 0; c < 4; c++) acc[i][j][c] = 0.f;

    const int niter = K / BK;

    auto issue = [&](int it) {
        int k0 = it * BK;
        float* sa = smem + (it % 3) * STAGE;
        float* sb = sa + BM * PITCH;
#pragma unroll
        for (int p = 0; p < BM / 32; p++) {
            int r = p * 32 + lrow;
            uint32_t dst = (uint32_t)__cvta_generic_to_shared(sa + r * PITCH + lcol);
            cp_async16(dst, A + (size_t)(m0 + r) * K + k0 + lcol, 16);
        }
#pragma unroll
        for (int p = 0; p < 4; p++) {
            int r = p * 32 + lrow;
            int gn = n0 + r;
            uint32_t dst = (uint32_t)__cvta_generic_to_shared(sb + r * PITCH + lcol);
            const float* src = W + (size_t)(gn < N ? gn : (N - 1)) * K + k0 + lcol;
            cp_async16(dst, src, gn < N ? 16 : 0);
        }
    };

    issue(0); cp_commit();
    if (niter > 1) { issue(1); cp_commit(); }

    for (int it = 0; it < niter; ++it) {
        if (it + 2 < niter) {
            issue(it + 2);
            cp_commit();
            cp_wait<2>();
        } else if (it + 1 < niter) {
            cp_wait<1>();
        } else {
            cp_wait<0>();
        }
        __syncthreads();

        const float* sa = smem + (it % 3) * STAGE;
        const float* sb = sa + BM * PITCH;

#pragma unroll
        for (int k8 = 0; k8 < 4; k8++) {
            int kb = k8 * 8;
            unsigned a[MT][4], b[4][2];
#pragma unroll
            for (int mt = 0; mt < MT; mt++) {
                int m = wm + mt * 16;
                a[mt][0] = f2tf32(sa[(m + g) * PITCH + kb + tig]);
                a[mt][1] = f2tf32(sa[(m + g + 8) * PITCH + kb + tig]);
                a[mt][2] = f2tf32(sa[(m + g) * PITCH + kb + tig + 4]);
                a[mt][3] = f2tf32(sa[(m + g + 8) * PITCH + kb + tig + 4]);
            }
#pragma unroll
            for (int nt = 0; nt < 4; nt++) {
                int n = wn + nt * 8;
                b[nt][0] = f2tf32(sb[(n + g) * PITCH + kb + tig]);
                b[nt][1] = f2tf32(sb[(n + g) * PITCH + kb + tig + 4]);
            }
#pragma unroll
            for (int mt = 0; mt < MT; mt++)
#pragma unroll
                for (int nt = 0; nt < 4; nt++) {
                    asm volatile(
                        "mma.sync.aligned.m16n8k8.row.col.f32.tf32.tf32.f32 "
                        "{%0,%1,%2,%3}, {%4,%5,%6,%7}, {%8,%9}, {%0,%1,%2,%3};\n"
                        : "+f"(acc[mt][nt][0]), "+f"(acc[mt][nt][1]),
                          "+f"(acc[mt][nt][2]), "+f"(acc[mt][nt][3])
                        : "r"(a[mt][0]), "r"(a[mt][1]), "r"(a[mt][2]), "r"(a[mt][3]),
                          "r"(b[nt][0]), "r"(b[nt][1]));
                }
        }
        __syncthreads();
    }

    // epilogue
#pragma unroll
    for (int mt = 0; mt < MT; mt++) {
#pragma unroll
        for (int nt = 0; nt < 4; nt++) {
            int ng = n0 + wn + nt * 8 + 2 * tig;
            if (ng >= N) continue;
#pragma unroll
            for (int half = 0; half < 2; half++) {
                int mg = m0 + wm + mt * 16 + g + half * 8;
                float v0 = acc[mt][nt][half * 2 + 0];
                float v1 = acc[mt][nt][half * 2 + 1];
                if (bias) { v0 += bias[ng]; v1 += bias[ng + 1]; }
                size_t off = (size_t)mg * N + ng;
                if (mode == 1) {
                    v0 = other[off]     * sigmoidf_(v0);
                    v1 = other[off + 1] * sigmoidf_(v1);
                } else if (mode == 2) {
                    v0 += other[off];
                    v1 += other[off + 1];
                }
                *(float2*)(C + off) = make_float2(v0, v1);
            }
        }
    }
}

// ---------------- dual TF32 GEMM: gated = (A@W1^T+b1) * sigmoid(A@W2^T+b2) ----------------
__global__ __launch_bounds__(256, 2)
void tf32_dual_gemm(const float* __restrict__ A,
                    const float* __restrict__ W1, const float* __restrict__ b1,
                    const float* __restrict__ W2, const float* __restrict__ b2,
                    float* __restrict__ C)
{
    constexpr int BM = 64, BN = 128, BK = 32, MT = 2;
    constexpr int PITCH = 36;
    constexpr int STAGE = (BM + 2 * BN) * PITCH;
    const int N = HID, K = IN_DIM;

    extern __shared__ float smem[];

    int tid  = threadIdx.x;
    int warp = tid >> 5, lane = tid & 31;
    int g    = lane >> 2, tig = lane & 3;
    int wm   = (warp >> 2) * (MT * 16);
    int wn   = (warp & 3) * 32;
    int m0   = blockIdx.y * BM;
    int n0   = blockIdx.x * BN;

    int lrow = tid >> 3;
    int lcol = (tid & 7) * 4;

    float acc1[MT][4][4], acc2[MT][4][4];
#pragma unroll
    for (int i = 0; i < MT; i++)
#pragma unroll
        for (int j = 0; j < 4; j++)
#pragma unroll
            for (int c = 0; c < 4; c++) { acc1[i][j][c] = 0.f; acc2[i][j][c] = 0.f; }

    const int niter = K / BK;

    auto issue = [&](int it, int buf) {
        int k0 = it * BK;
        float* sa  = smem + buf * STAGE;
        float* sb1 = sa + BM * PITCH;
        float* sb2 = sb1 + BN * PITCH;
#pragma unroll
        for (int p = 0; p < 2; p++) {
            int r = p * 32 + lrow;
            uint32_t dst = (uint32_t)__cvta_generic_to_shared(sa + r * PITCH + lcol);
            cp_async16(dst, A + (size_t)(m0 + r) * K + k0 + lcol, 16);
        }
#pragma unroll
        for (int p = 0; p < 4; p++) {
            int r = p * 32 + lrow;
            uint32_t d1 = (uint32_t)__cvta_generic_to_shared(sb1 + r * PITCH + lcol);
            cp_async16(d1, W1 + (size_t)(n0 + r) * K + k0 + lcol, 16);
            uint32_t d2 = (uint32_t)__cvta_generic_to_shared(sb2 + r * PITCH + lcol);
            cp_async16(d2, W2 + (size_t)(n0 + r) * K + k0 + lcol, 16);
        }
    };

    issue(0, 0);
    cp_commit();

    for (int it = 0; it < niter; ++it) {
        int buf = it & 1;
        if (it + 1 < niter) {
            issue(it + 1, buf ^ 1);
            cp_commit();
            cp_wait<1>();
        } else {
            cp_wait<0>();
        }
        __syncthreads();

        const float* sa  = smem + buf * STAGE;
        const float* sb1 = sa + BM * PITCH;
        const float* sb2 = sb1 + BN * PITCH;

#pragma unroll
        for (int k8 = 0; k8 < 4; k8++) {
            int kb = k8 * 8;
            unsigned a[MT][4];
#pragma unroll
            for (int mt = 0; mt < MT; mt++) {
                int m = wm + mt * 16;
                a[mt][0] = f2tf32(sa[(m + g) * PITCH + kb + tig]);
                a[mt][1] = f2tf32(sa[(m + g + 8) * PITCH + kb + tig]);
                a[mt][2] = f2tf32(sa[(m + g) * PITCH + kb + tig + 4]);
                a[mt][3] = f2tf32(sa[(m + g + 8) * PITCH + kb + tig + 4]);
            }
#pragma unroll
            for (int nt = 0; nt < 4; nt++) {
                int n = wn + nt * 8;
                unsigned p0 = f2tf32(sb1[(n + g) * PITCH + kb + tig]);
                unsigned p1 = f2tf32(sb1[(n + g) * PITCH + kb + tig + 4]);
                unsigned q0 = f2tf32(sb2[(n + g) * PITCH + kb + tig]);
                unsigned q1 = f2tf32(sb2[(n + g) * PITCH + kb + tig + 4]);
#pragma unroll
                for (int mt = 0; mt < MT; mt++) {
                    asm volatile(
                        "mma.sync.aligned.m16n8k8.row.col.f32.tf32.tf32.f32 "
                        "{%0,%1,%2,%3}, {%4,%5,%6,%7}, {%8,%9}, {%0,%1,%2,%3};\n"
                        : "+f"(acc1[mt][nt][0]), "+f"(acc1[mt][nt][1]),
                          "+f"(acc1[mt][nt][2]), "+f"(acc1[mt][nt][3])
                        : "r"(a[mt][0]), "r"(a[mt][1]), "r"(a[mt][2]), "r"(a[mt][3]),
                          "r"(p0), "r"(p1));
                    asm volatile(
                        "mma.sync.aligned.m16n8k8.row.col.f32.tf32.tf32.f32 "
                        "{%0,%1,%2,%3}, {%4,%5,%6,%7}, {%8,%9}, {%0,%1,%2,%3};\n"
                        : "+f"(acc2[mt][nt][0]), "+f"(acc2[mt][nt][1]),
                          "+f"(acc2[mt][nt][2]), "+f"(acc2[mt][nt][3])
                        : "r"(a[mt][0]), "r"(a[mt][1]), "r"(a[mt][2]), "r"(a[mt][3]),
                          "r"(q0), "r"(q1));
                }
            }
        }
        __syncthreads();
    }

#pragma unroll
    for (int mt = 0; mt < MT; mt++) {
#pragma unroll
        for (int nt = 0; nt < 4; nt++) {
            int ng = n0 + wn + nt * 8 + 2 * tig;
#pragma unroll
            for (int half = 0; half < 2; half++) {
                int mg = m0 + wm + mt * 16 + g + half * 8;
                float u0 = acc1[mt][nt][half * 2 + 0] + b1[ng];
                float u1 = acc1[mt][nt][half * 2 + 1] + b1[ng + 1];
                float v0 = acc2[mt][nt][half * 2 + 0] + b2[ng];
                float v1 = acc2[mt][nt][half * 2 + 1] + b2[ng + 1];
                size_t off = (size_t)mg * N + ng;
                *(float2*)(C + off) = make_float2(u0 * sigmoidf_(v0), u1 * sigmoidf_(v1));
            }
        }
    }
}

// ---------------- mega-fused: conv + dt + SSM update + gate + group RMS norm ----------------
// One block per (batch, group).  512 threads.
// In-block: depthwise conv (640 channels: 512 x + 64 B + 64 C) + new_conv write,
// then SSM state update (8 heads x 64p x 64n), C-contraction, silu(z) gate, group RMS.
__global__ __launch_bounds__(512)
void ssm_mega(const float* __restrict__ conv_state,
              const float* __restrict__ conv_w,
              const float* __restrict__ conv_b,
              const float* __restrict__ ssm_state,
              const float* __restrict__ zx,
              const float* __restrict__ A_log,
              const float* __restrict__ Dp,
              const float* __restrict__ dt_bias,
              const float* __restrict__ norm_w,
              float* __restrict__ new_conv_out,
              float* __restrict__ new_ssm_out,
              float* __restrict__ yn) {
    int bg = blockIdx.x;
    int b = bg >> 2, g = bg & 3;
    int tid = threadIdx.x;
    int h_loc = tid >> 6;
    int t64 = tid & 63;
    int tn = t64 & 15;
    int pg = t64 >> 4;
    int h = g * 8 + h_loc;

    __shared__ float Bsh[DS], Csh[DS], Xsh[512], Zsh[512], Yv[512];
    __shared__ float dtsh[8], dAsh[8], Dpsh[8];

    // ---- fused depthwise conv for this block's 640 channels ----
    // t in [0,512): x channel c = g*512+t ; t in [512,576): B ; t in [576,640): C
    auto do_conv = [&](int t) {
        int c;
        if (t < 512)      c = g * 512 + t;
        else if (t < 576) c = DIN + g * DS + (t - 512);
        else              c = DIN + NG * DS + g * DS + (t - 576);
        int idx = b * CONV_DIM + c;
        float4 cs = ((const float4*)conv_state)[idx];
        float xn = zx[(size_t)b * DINP + DIN + c];
        float4 w = ((const float4*)conv_w)[c];
        float acc = cs.y * w.x + cs.z * w.y + cs.w * w.z + xn * w.w + conv_b[c];
        float act = siluf_(acc);
        ((float4*)new_conv_out)[idx] = make_float4(cs.y, cs.z, cs.w, xn);
        if (t < 512)      Xsh[t] = act;
        else if (t < 576) Bsh[t - 512] = act;
        else              Csh[t - 576] = act;
    };
    do_conv(tid);
    if (tid < 128) do_conv(tid + 512);

    Zsh[tid] = zx[(size_t)b * DINP + g * 512 + tid];
    if (tid < 8) {
        int hh = g * 8 + tid;
        float raw = zx[(size_t)b * DINP + DIN + CONV_DIM + hh] + dt_bias[hh];
        float sp = (raw > 20.f) ? raw : log1pf(expf(raw));
        dtsh[tid] = sp;
        dAsh[tid] = expf(sp * -expf(A_log[hh]));
        Dpsh[tid] = Dp[hh];
    }
    __syncthreads();

    float4 B4 = *(const float4*)&Bsh[tn * 4];
    float4 C4 = *(const float4*)&Csh[tn * 4];
    float dtv = dtsh[h_loc], dAv = dAsh[h_loc];

    size_t head_base = (((size_t)b * NH + h) * HD) * DS;

    float part[16];
#pragma unroll
    for (int i = 0; i < 16; i++) {
        int p = pg * 16 + i;
        size_t off = head_base + (size_t)p * DS + tn * 4;
        float4 s = *(const float4*)(ssm_state + off);
        float coef = dtv * Xsh[h_loc * 64 + p];
        float4 ns;
        ns.x = fmaf(s.x, dAv, coef * B4.x);
        ns.y = fmaf(s.y, dAv, coef * B4.y);
        ns.z = fmaf(s.z, dAv, coef * B4.z);
        ns.w = fmaf(s.w, dAv, coef * B4.w);
        *(float4*)(new_ssm_out + off) = ns;
        part[i] = ns.x * C4.x + ns.y * C4.y + ns.z * C4.z + ns.w * C4.w;
    }

#pragma unroll
    for (int i = 0; i < 16; i++) {
        float v = part[i];
        v += __shfl_down_sync(0xffffffffu, v, 8, 16);
        v += __shfl_down_sync(0xffffffffu, v, 4, 16);
        v += __shfl_down_sync(0xffffffffu, v, 2, 16);
        v += __shfl_down_sync(0xffffffffu, v, 1, 16);
        part[i] = v;
    }
    if (tn == 0) {
        float dp = Dpsh[h_loc];
#pragma unroll
        for (int i = 0; i < 16; i++) {
            int p = pg * 16 + i;
            float x = Xsh[h_loc * 64 + p];
            float y = part[i] + dp * x;
            float z = Zsh[h_loc * 64 + p];
            Yv[h_loc * 64 + p] = y * siluf_(z);
        }
    }
    __syncthreads();

    float v = Yv[tid];
    float ss = v * v;
    for (int o = 16; o; o >>= 1) ss += __shfl_down_sync(0xffffffffu, ss, o);
    __shared__ float wsums[16];
    int wid = tid >> 5, lid = tid & 31;
    if (lid == 0) wsums[wid] = ss;
    __syncthreads();
    __shared__ float scale_s;
    if (tid == 0) {
        float tot = 0.f;
        for (int i = 0; i < 16; i++) tot += wsums[i];
        scale_s = rsqrtf(tot / 512.f + EPS);
    }
    __syncthreads();
    yn[(size_t)b * DIN + g * 512 + tid] = v * scale_s * norm_w[g * 512 + tid];
}

// ---------------- launch ----------------
extern "C" void kernel_launch(void* const* d_in, const int* in_sizes, int n_in,
                              void* d_out, int out_size) {
    const float* frame_feat   = (const float*)d_in[0];
    const float* conv_state   = (const float*)d_in[1];
    const float* ssm_state    = (const float*)d_in[2];
    const float* ln_w         = (const float*)d_in[3];
    const float* ln_b         = (const float*)d_in[4];
    const float* w_in_gate    = (const float*)d_in[5];
    const float* b_in_gate    = (const float*)d_in[6];
    const float* w_input_proj = (const float*)d_in[7];
    const float* b_input_proj = (const float*)d_in[8];
    const float* w_in_proj    = (const float*)d_in[9];
    const float* conv_w       = (const float*)d_in[10];
    const float* conv_b       = (const float*)d_in[11];
    const float* A_log        = (const float*)d_in[12];
    const float* Dp           = (const float*)d_in[13];
    const float* dt_bias      = (const float*)d_in[14];
    const float* norm_w       = (const float*)d_in[15];
    const float* w_out_proj   = (const float*)d_in[16];
    const float* w_out_gate   = (const float*)d_in[17];
    const float* b_out_gate   = (const float*)d_in[18];
    const float* w_proj       = (const float*)d_in[19];
    const float* b_proj       = (const float*)d_in[20];

    float* out = (float*)d_out;
    float* out_clip = out;                                      // [1024, 512]
    float* out_conv = out + (size_t)BATCH * CLIP;               // [1024, 2560, 4]
    float* out_ssm  = out_conv + (size_t)BATCH * CONV_DIM * DC; // [1024, 32, 64, 64]

    float *x, *gated, *zx, *yn, *outpre, *outf;
    cudaGetSymbolAddress((void**)&x,      g_x);
    cudaGetSymbolAddress((void**)&gated,  g_gated);
    cudaGetSymbolAddress((void**)&zx,     g_zx);
    cudaGetSymbolAddress((void**)&yn,     g_yn);
    cudaGetSymbolAddress((void**)&outpre, g_outpre);
    cudaGetSymbolAddress((void**)&outf,   g_outf);

    const int SMEM64   = (64  + 128) * 36 * 4 * 3;       // 82944  (3-stage)
    const int SMEM128  = (128 + 128) * 36 * 4 * 3;       // 110592 (3-stage)
    const int SMEMDUAL = (64 + 256) * 36 * 4 * 2;        // 92160  (2-stage)
    static bool attr_set = false;
    if (!attr_set) {
        cudaFuncSetAttribute(tf32_gemm<64>,  cudaFuncAttributeMaxDynamicSharedMemorySize, SMEM64);
        cudaFuncSetAttribute(tf32_gemm<128>, cudaFuncAttributeMaxDynamicSharedMemorySize, SMEM128);
        cudaFuncSetAttribute(tf32_dual_gemm, cudaFuncAttributeMaxDynamicSharedMemorySize, SMEMDUAL);
        attr_set = true;
    }

    // 1. layernorm
    ln_kernel<<<BATCH, 256>>>(frame_feat, ln_w, ln_b, x);

    // 2. gated = (x@w_input_proj^T+b) * sigmoid(x@w_in_gate^T+b)
    tf32_dual_gemm<<<dim3(HID / 128, BATCH / 64), 256, SMEMDUAL>>>(
        x, w_input_proj, b_input_proj, w_in_gate, b_in_gate, gated);

    // 3. zxbcdt = gated @ w_in_proj^T
    tf32_gemm<128><<<dim3((DINP + 127) / 128, BATCH / 128), 256, SMEM128>>>(
        gated, w_in_proj, nullptr, nullptr, zx, BATCH, DINP, HID, 0);

    // 4. mega-fused conv + dt + SSM + gate + rmsnorm (writes new_conv + new_ssm + yn)
    ssm_mega<<<BATCH * NG, 512>>>(conv_state, conv_w, conv_b, ssm_state, zx,
                                  A_log, Dp, dt_bias, norm_w,
                                  out_conv, out_ssm, yn);

    // 5. outpre = yn @ w_out_proj^T + gated
    tf32_gemm<64><<<dim3(HID / 128, BATCH / 64), 256, SMEM64>>>(
        yn, w_out_proj, nullptr, gated, outpre, BATCH, HID, DIN, 2);

    // 6. outf = outpre * sigmoid(outpre @ w_out_gate^T + b)
    tf32_gemm<64><<<dim3(HID / 128, BATCH / 64), 256, SMEM64>>>(
        outpre, w_out_gate, b_out_gate, outpre, outf, BATCH, HID, HID, 1);

    // 7. clip = outf @ w_proj^T + b
    tf32_gemm<64><<<dim3(CLIP / 128, BATCH / 64), 256, SMEM64>>>(
        outf, w_proj, b_proj, nullptr, out_clip, BATCH, CLIP, HID, 0);
}

// round 17
// speedup vs baseline: 1.0491x; 1.0491x over previous
#include <cuda_runtime.h>
#include <math.h>
#include <stdint.h>

#define IN_DIM   768
#define HID      1024
#define CLIP     512
#define NG       4
#define DS       64
#define DC       4
#define HD       64
#define DIN      2048
#define NH       32
#define CONV_DIM 2560
#define DINP     4640
#define BATCH    1024
#define EPS      1e-5f

// ---------------- scratch ----------------
__device__ float g_x[BATCH * IN_DIM];
__device__ float g_gated[BATCH * HID];
__device__ float g_zx[BATCH * DINP];
__device__ float g_yn[BATCH * DIN];
__device__ float g_outpre[BATCH * HID];
__device__ float g_outf[BATCH * HID];

__device__ __forceinline__ float sigmoidf_(float v) { return 1.0f / (1.0f + expf(-v)); }
__device__ __forceinline__ float siluf_(float v)    { return v / (1.0f + expf(-v)); }

__device__ __forceinline__ unsigned f2tf32(float x) {
    unsigned r;
    asm("cvt.rna.tf32.f32 %0, %1;" : "=r"(r) : "f"(x));
    return r;
}

__device__ __forceinline__ void cp_async16(uint32_t dst, const void* src, int src_bytes) {
    asm volatile("cp.async.cg.shared.global [%0], [%1], 16, %2;\n"
                 :: "r"(dst), "l"(src), "r"(src_bytes));
}
__device__ __forceinline__ void cp_commit() {
    asm volatile("cp.async.commit_group;\n");
}
template<int N>
__device__ __forceinline__ void cp_wait() {
    asm volatile("cp.async.wait_group %0;\n" :: "n"(N));
}

// ---------------- layernorm ----------------
__global__ void ln_kernel(const float* __restrict__ ff,
                          const float* __restrict__ w,
                          const float* __restrict__ b,
                          float* __restrict__ out) {
    int row = blockIdx.x;
    const float* in = ff + (size_t)row * IN_DIM;
    float* o = out + (size_t)row * IN_DIM;
    int tid = threadIdx.x;               // 256 threads
    float v0 = in[tid], v1 = in[tid + 256], v2 = in[tid + 512];
    float s = v0 + v1 + v2;
    float s2 = v0 * v0 + v1 * v1 + v2 * v2;
    for (int o2 = 16; o2; o2 >>= 1) {
        s  += __shfl_down_sync(0xffffffffu, s,  o2);
        s2 += __shfl_down_sync(0xffffffffu, s2, o2);
    }
    __shared__ float ss[8], ss2[8];
    int wid = tid >> 5, lid = tid & 31;
    if (lid == 0) { ss[wid] = s; ss2[wid] = s2; }
    __syncthreads();
    __shared__ float mu_s, rstd_s;
    if (tid == 0) {
        float ts = 0.f, ts2 = 0.f;
        for (int i = 0; i < 8; i++) { ts += ss[i]; ts2 += ss2[i]; }
        float mu = ts / IN_DIM;
        float var = ts2 / IN_DIM - mu * mu;
        mu_s = mu;
        rstd_s = rsqrtf(var + EPS);
    }
    __syncthreads();
    float mu = mu_s, rstd = rstd_s;
    o[tid]       = (v0 - mu) * rstd * w[tid]       + b[tid];
    o[tid + 256] = (v1 - mu) * rstd * w[tid + 256] + b[tid + 256];
    o[tid + 512] = (v2 - mu) * rstd * w[tid + 512] + b[tid + 512];
}

// ---------------- TF32 tensor-core GEMM, cp.async 3-stage pipelined ----------------
template<int BM>
__global__ __launch_bounds__(256, 2)
void tf32_gemm(const float* __restrict__ A, const float* __restrict__ W,
               const float* __restrict__ bias, const float* __restrict__ other,
               float* __restrict__ C, int M, int N, int K, int mode)
{
    constexpr int BN = 128;
    constexpr int BK = 32;
    constexpr int MT = BM / 32;
    constexpr int PITCH = 36;
    constexpr int STAGE = (BM + BN) * PITCH;

    extern __shared__ float smem[];

    int tid  = threadIdx.x;
    int warp = tid >> 5, lane = tid & 31;
    int g    = lane >> 2, tig = lane & 3;
    int wm   = (warp >> 2) * (MT * 16);
    int wn   = (warp & 3) * 32;
    int m0   = blockIdx.y * BM;
    int n0   = blockIdx.x * BN;

    int lrow = tid >> 3;          // 0..31
    int lcol = (tid & 7) * 4;     // 0,4,...,28

    float acc[MT][4][4];
#pragma unroll
    for (int i = 0; i < MT; i++)
#pragma unroll
        for (int j = 0; j < 4; j++)
#pragma unroll
            for (int c = 0; c < 4; c++) acc[i][j][c] = 0.f;

    const int niter = K / BK;

    auto issue = [&](int it) {
        int k0 = it * BK;
        float* sa = smem + (it % 3) * STAGE;
        float* sb = sa + BM * PITCH;
#pragma unroll
        for (int p = 0; p < BM / 32; p++) {
            int r = p * 32 + lrow;
            uint32_t dst = (uint32_t)__cvta_generic_to_shared(sa + r * PITCH + lcol);
            cp_async16(dst, A + (size_t)(m0 + r) * K + k0 + lcol, 16);
        }
#pragma unroll
        for (int p = 0; p < 4; p++) {
            int r = p * 32 + lrow;
            int gn = n0 + r;
            uint32_t dst = (uint32_t)__cvta_generic_to_shared(sb + r * PITCH + lcol);
            const float* src = W + (size_t)(gn < N ? gn : (N - 1)) * K + k0 + lcol;
            cp_async16(dst, src, gn < N ? 16 : 0);
        }
    };

    issue(0); cp_commit();
    if (niter > 1) { issue(1); cp_commit(); }

    for (int it = 0; it < niter; ++it) {
        if (it + 2 < niter) {
            issue(it + 2);
            cp_commit();
            cp_wait<2>();
        } else if (it + 1 < niter) {
            cp_wait<1>();
        } else {
            cp_wait<0>();
        }
        __syncthreads();

        const float* sa = smem + (it % 3) * STAGE;
        const float* sb = sa + BM * PITCH;

#pragma unroll
        for (int k8 = 0; k8 < 4; k8++) {
            int kb = k8 * 8;
            unsigned a[MT][4], b[4][2];
#pragma unroll
            for (int mt = 0; mt < MT; mt++) {
                int m = wm + mt * 16;
                a[mt][0] = f2tf32(sa[(m + g) * PITCH + kb + tig]);
                a[mt][1] = f2tf32(sa[(m + g + 8) * PITCH + kb + tig]);
                a[mt][2] = f2tf32(sa[(m + g) * PITCH + kb + tig + 4]);
                a[mt][3] = f2tf32(sa[(m + g + 8) * PITCH + kb + tig + 4]);
            }
#pragma unroll
            for (int nt = 0; nt < 4; nt++) {
                int n = wn + nt * 8;
                b[nt][0] = f2tf32(sb[(n + g) * PITCH + kb + tig]);
                b[nt][1] = f2tf32(sb[(n + g) * PITCH + kb + tig + 4]);
            }
#pragma unroll
            for (int mt = 0; mt < MT; mt++)
#pragma unroll
                for (int nt = 0; nt < 4; nt++) {
                    asm volatile(
                        "mma.sync.aligned.m16n8k8.row.col.f32.tf32.tf32.f32 "
                        "{%0,%1,%2,%3}, {%4,%5,%6,%7}, {%8,%9}, {%0,%1,%2,%3};\n"
                        : "+f"(acc[mt][nt][0]), "+f"(acc[mt][nt][1]),
                          "+f"(acc[mt][nt][2]), "+f"(acc[mt][nt][3])
                        : "r"(a[mt][0]), "r"(a[mt][1]), "r"(a[mt][2]), "r"(a[mt][3]),
                          "r"(b[nt][0]), "r"(b[nt][1]));
                }
        }
        __syncthreads();
    }

    // epilogue
#pragma unroll
    for (int mt = 0; mt < MT; mt++) {
#pragma unroll
        for (int nt = 0; nt < 4; nt++) {
            int ng = n0 + wn + nt * 8 + 2 * tig;
            if (ng >= N) continue;
#pragma unroll
            for (int half = 0; half < 2; half++) {
                int mg = m0 + wm + mt * 16 + g + half * 8;
                float v0 = acc[mt][nt][half * 2 + 0];
                float v1 = acc[mt][nt][half * 2 + 1];
                if (bias) { v0 += bias[ng]; v1 += bias[ng + 1]; }
                size_t off = (size_t)mg * N + ng;
                if (mode == 1) {
                    v0 = other[off]     * sigmoidf_(v0);
                    v1 = other[off + 1] * sigmoidf_(v1);
                } else if (mode == 2) {
                    v0 += other[off];
                    v1 += other[off + 1];
                }
                *(float2*)(C + off) = make_float2(v0, v1);
            }
        }
    }
}

// ---------------- dual TF32 GEMM: gated = (A@W1^T+b1) * sigmoid(A@W2^T+b2) ----------------
__global__ __launch_bounds__(256, 2)
void tf32_dual_gemm(const float* __restrict__ A,
                    const float* __restrict__ W1, const float* __restrict__ b1,
                    const float* __restrict__ W2, const float* __restrict__ b2,
                    float* __restrict__ C)
{
    constexpr int BM = 64, BN = 128, BK = 32, MT = 2;
    constexpr int PITCH = 36;
    constexpr int STAGE = (BM + 2 * BN) * PITCH;
    const int N = HID, K = IN_DIM;

    extern __shared__ float smem[];

    int tid  = threadIdx.x;
    int warp = tid >> 5, lane = tid & 31;
    int g    = lane >> 2, tig = lane & 3;
    int wm   = (warp >> 2) * (MT * 16);
    int wn   = (warp & 3) * 32;
    int m0   = blockIdx.y * BM;
    int n0   = blockIdx.x * BN;

    int lrow = tid >> 3;
    int lcol = (tid & 7) * 4;

    float acc1[MT][4][4], acc2[MT][4][4];
#pragma unroll
    for (int i = 0; i < MT; i++)
#pragma unroll
        for (int j = 0; j < 4; j++)
#pragma unroll
            for (int c = 0; c < 4; c++) { acc1[i][j][c] = 0.f; acc2[i][j][c] = 0.f; }

    const int niter = K / BK;

    auto issue = [&](int it, int buf) {
        int k0 = it * BK;
        float* sa  = smem + buf * STAGE;
        float* sb1 = sa + BM * PITCH;
        float* sb2 = sb1 + BN * PITCH;
#pragma unroll
        for (int p = 0; p < 2; p++) {
            int r = p * 32 + lrow;
            uint32_t dst = (uint32_t)__cvta_generic_to_shared(sa + r * PITCH + lcol);
            cp_async16(dst, A + (size_t)(m0 + r) * K + k0 + lcol, 16);
        }
#pragma unroll
        for (int p = 0; p < 4; p++) {
            int r = p * 32 + lrow;
            uint32_t d1 = (uint32_t)__cvta_generic_to_shared(sb1 + r * PITCH + lcol);
            cp_async16(d1, W1 + (size_t)(n0 + r) * K + k0 + lcol, 16);
            uint32_t d2 = (uint32_t)__cvta_generic_to_shared(sb2 + r * PITCH + lcol);
            cp_async16(d2, W2 + (size_t)(n0 + r) * K + k0 + lcol, 16);
        }
    };

    issue(0, 0);
    cp_commit();

    for (int it = 0; it < niter; ++it) {
        int buf = it & 1;
        if (it + 1 < niter) {
            issue(it + 1, buf ^ 1);
            cp_commit();
            cp_wait<1>();
        } else {
            cp_wait<0>();
        }
        __syncthreads();

        const float* sa  = smem + buf * STAGE;
        const float* sb1 = sa + BM * PITCH;
        const float* sb2 = sb1 + BN * PITCH;

#pragma unroll
        for (int k8 = 0; k8 < 4; k8++) {
            int kb = k8 * 8;
            unsigned a[MT][4];
#pragma unroll
            for (int mt = 0; mt < MT; mt++) {
                int m = wm + mt * 16;
                a[mt][0] = f2tf32(sa[(m + g) * PITCH + kb + tig]);
                a[mt][1] = f2tf32(sa[(m + g + 8) * PITCH + kb + tig]);
                a[mt][2] = f2tf32(sa[(m + g) * PITCH + kb + tig + 4]);
                a[mt][3] = f2tf32(sa[(m + g + 8) * PITCH + kb + tig + 4]);
            }
#pragma unroll
            for (int nt = 0; nt < 4; nt++) {
                int n = wn + nt * 8;
                unsigned p0 = f2tf32(sb1[(n + g) * PITCH + kb + tig]);
                unsigned p1 = f2tf32(sb1[(n + g) * PITCH + kb + tig + 4]);
                unsigned q0 = f2tf32(sb2[(n + g) * PITCH + kb + tig]);
                unsigned q1 = f2tf32(sb2[(n + g) * PITCH + kb + tig + 4]);
#pragma unroll
                for (int mt = 0; mt < MT; mt++) {
                    asm volatile(
                        "mma.sync.aligned.m16n8k8.row.col.f32.tf32.tf32.f32 "
                        "{%0,%1,%2,%3}, {%4,%5,%6,%7}, {%8,%9}, {%0,%1,%2,%3};\n"
                        : "+f"(acc1[mt][nt][0]), "+f"(acc1[mt][nt][1]),
                          "+f"(acc1[mt][nt][2]), "+f"(acc1[mt][nt][3])
                        : "r"(a[mt][0]), "r"(a[mt][1]), "r"(a[mt][2]), "r"(a[mt][3]),
                          "r"(p0), "r"(p1));
                    asm volatile(
                        "mma.sync.aligned.m16n8k8.row.col.f32.tf32.tf32.f32 "
                        "{%0,%1,%2,%3}, {%4,%5,%6,%7}, {%8,%9}, {%0,%1,%2,%3};\n"
                        : "+f"(acc2[mt][nt][0]), "+f"(acc2[mt][nt][1]),
                          "+f"(acc2[mt][nt][2]), "+f"(acc2[mt][nt][3])
                        : "r"(a[mt][0]), "r"(a[mt][1]), "r"(a[mt][2]), "r"(a[mt][3]),
                          "r"(q0), "r"(q1));
                }
            }
        }
        __syncthreads();
    }

#pragma unroll
    for (int mt = 0; mt < MT; mt++) {
#pragma unroll
        for (int nt = 0; nt < 4; nt++) {
            int ng = n0 + wn + nt * 8 + 2 * tig;
#pragma unroll
            for (int half = 0; half < 2; half++) {
                int mg = m0 + wm + mt * 16 + g + half * 8;
                float u0 = acc1[mt][nt][half * 2 + 0] + b1[ng];
                float u1 = acc1[mt][nt][half * 2 + 1] + b1[ng + 1];
                float v0 = acc2[mt][nt][half * 2 + 0] + b2[ng];
                float v1 = acc2[mt][nt][half * 2 + 1] + b2[ng + 1];
                size_t off = (size_t)mg * N + ng;
                *(float2*)(C + off) = make_float2(u0 * sigmoidf_(v0), u1 * sigmoidf_(v1));
            }
        }
    }
}

// ---------------- mega-fused: conv + dt + SSM update + gate + group RMS norm ----------------
// One block per (batch, group), 512 threads, 2 CTAs/SM (regs capped).
__global__ __launch_bounds__(512, 2)
void ssm_mega(const float* __restrict__ conv_state,
              const float* __restrict__ conv_w,
              const float* __restrict__ conv_b,
              const float* __restrict__ ssm_state,
              const float* __restrict__ zx,
              const float* __restrict__ A_log,
              const float* __restrict__ Dp,
              const float* __restrict__ dt_bias,
              const float* __restrict__ norm_w,
              float* __restrict__ new_conv_out,
              float* __restrict__ new_ssm_out,
              float* __restrict__ yn) {
    int bg = blockIdx.x;
    int b = bg >> 2, g = bg & 3;
    int tid = threadIdx.x;
    int h_loc = tid >> 6;
    int t64 = tid & 63;
    int tn = t64 & 15;
    int pg = t64 >> 4;
    int h = g * 8 + h_loc;

    __shared__ float Bsh[DS], Csh[DS], Xsh[512], Zsh[512], Yv[512];
    __shared__ float dtsh[8], dAsh[8], Dpsh[8];

    // ---- fused depthwise conv for this block's 640 channels ----
    auto do_conv = [&](int t) {
        int c;
        if (t < 512)      c = g * 512 + t;
        else if (t < 576) c = DIN + g * DS + (t - 512);
        else              c = DIN + NG * DS + g * DS + (t - 576);
        int idx = b * CONV_DIM + c;
        float4 cs = ((const float4*)conv_state)[idx];
        float xn = zx[(size_t)b * DINP + DIN + c];
        float4 w = ((const float4*)conv_w)[c];
        float acc = cs.y * w.x + cs.z * w.y + cs.w * w.z + xn * w.w + conv_b[c];
        float act = siluf_(acc);
        ((float4*)new_conv_out)[idx] = make_float4(cs.y, cs.z, cs.w, xn);
        if (t < 512)      Xsh[t] = act;
        else if (t < 576) Bsh[t - 512] = act;
        else              Csh[t - 576] = act;
    };
    do_conv(tid);
    if (tid < 128) do_conv(tid + 512);

    Zsh[tid] = zx[(size_t)b * DINP + g * 512 + tid];
    if (tid < 8) {
        int hh = g * 8 + tid;
        float raw = zx[(size_t)b * DINP + DIN + CONV_DIM + hh] + dt_bias[hh];
        float sp = (raw > 20.f) ? raw : log1pf(expf(raw));
        dtsh[tid] = sp;
        dAsh[tid] = expf(sp * -expf(A_log[hh]));
        Dpsh[tid] = Dp[hh];
    }
    __syncthreads();

    float4 B4 = *(const float4*)&Bsh[tn * 4];
    float4 C4 = *(const float4*)&Csh[tn * 4];
    float dtv = dtsh[h_loc], dAv = dAsh[h_loc];
    float dp  = Dpsh[h_loc];

    size_t head_base = (((size_t)b * NH + h) * HD) * DS;

    // streaming state update; shuffle-reduce inside the loop to keep regs low
#pragma unroll
    for (int i = 0; i < 16; i++) {
        int p = pg * 16 + i;
        size_t off = head_base + (size_t)p * DS + tn * 4;
        float4 s = __ldcs((const float4*)(ssm_state + off));
        float coef = dtv * Xsh[h_loc * 64 + p];
        float4 ns;
        ns.x = fmaf(s.x, dAv, coef * B4.x);
        ns.y = fmaf(s.y, dAv, coef * B4.y);
        ns.z = fmaf(s.z, dAv, coef * B4.z);
        ns.w = fmaf(s.w, dAv, coef * B4.w);
        __stcs((float4*)(new_ssm_out + off), ns);
        float v = ns.x * C4.x + ns.y * C4.y + ns.z * C4.z + ns.w * C4.w;
        v += __shfl_down_sync(0xffffffffu, v, 8, 16);
        v += __shfl_down_sync(0xffffffffu, v, 4, 16);
        v += __shfl_down_sync(0xffffffffu, v, 2, 16);
        v += __shfl_down_sync(0xffffffffu, v, 1, 16);
        if (tn == 0) {
            float x = Xsh[h_loc * 64 + p];
            float y = v + dp * x;
            float z = Zsh[h_loc * 64 + p];
            Yv[h_loc * 64 + p] = y * siluf_(z);
        }
    }
    __syncthreads();

    float v = Yv[tid];
    float ss = v * v;
    for (int o = 16; o; o >>= 1) ss += __shfl_down_sync(0xffffffffu, ss, o);
    __shared__ float wsums[16];
    int wid = tid >> 5, lid = tid & 31;
    if (lid == 0) wsums[wid] = ss;
    __syncthreads();
    __shared__ float scale_s;
    if (tid == 0) {
        float tot = 0.f;
        for (int i = 0; i < 16; i++) tot += wsums[i];
        scale_s = rsqrtf(tot / 512.f + EPS);
    }
    __syncthreads();
    yn[(size_t)b * DIN + g * 512 + tid] = v * scale_s * norm_w[g * 512 + tid];
}

// ---------------- launch ----------------
extern "C" void kernel_launch(void* const* d_in, const int* in_sizes, int n_in,
                              void* d_out, int out_size) {
    const float* frame_feat   = (const float*)d_in[0];
    const float* conv_state   = (const float*)d_in[1];
    const float* ssm_state    = (const float*)d_in[2];
    const float* ln_w         = (const float*)d_in[3];
    const float* ln_b         = (const float*)d_in[4];
    const float* w_in_gate    = (const float*)d_in[5];
    const float* b_in_gate    = (const float*)d_in[6];
    const float* w_input_proj = (const float*)d_in[7];
    const float* b_input_proj = (const float*)d_in[8];
    const float* w_in_proj    = (const float*)d_in[9];
    const float* conv_w       = (const float*)d_in[10];
    const float* conv_b       = (const float*)d_in[11];
    const float* A_log        = (const float*)d_in[12];
    const float* Dp           = (const float*)d_in[13];
    const float* dt_bias      = (const float*)d_in[14];
    const float* norm_w       = (const float*)d_in[15];
    const float* w_out_proj   = (const float*)d_in[16];
    const float* w_out_gate   = (const float*)d_in[17];
    const float* b_out_gate   = (const float*)d_in[18];
    const float* w_proj       = (const float*)d_in[19];
    const float* b_proj       = (const float*)d_in[20];

    float* out = (float*)d_out;
    float* out_clip = out;                                      // [1024, 512]
    float* out_conv = out + (size_t)BATCH * CLIP;               // [1024, 2560, 4]
    float* out_ssm  = out_conv + (size_t)BATCH * CONV_DIM * DC; // [1024, 32, 64, 64]

    float *x, *gated, *zx, *yn, *outpre, *outf;
    cudaGetSymbolAddress((void**)&x,      g_x);
    cudaGetSymbolAddress((void**)&gated,  g_gated);
    cudaGetSymbolAddress((void**)&zx,     g_zx);
    cudaGetSymbolAddress((void**)&yn,     g_yn);
    cudaGetSymbolAddress((void**)&outpre, g_outpre);
    cudaGetSymbolAddress((void**)&outf,   g_outf);

    const int SMEM64   = (64  + 128) * 36 * 4 * 3;       // 82944  (3-stage)
    const int SMEM128  = (128 + 128) * 36 * 4 * 3;       // 110592 (3-stage)
    const int SMEMDUAL = (64 + 256) * 36 * 4 * 2;        // 92160  (2-stage)
    static bool attr_set = false;
    if (!attr_set) {
        cudaFuncSetAttribute(tf32_gemm<64>,  cudaFuncAttributeMaxDynamicSharedMemorySize, SMEM64);
        cudaFuncSetAttribute(tf32_gemm<128>, cudaFuncAttributeMaxDynamicSharedMemorySize, SMEM128);
        cudaFuncSetAttribute(tf32_dual_gemm, cudaFuncAttributeMaxDynamicSharedMemorySize, SMEMDUAL);
        attr_set = true;
    }

    // 1. layernorm
    ln_kernel<<<BATCH, 256>>>(frame_feat, ln_w, ln_b, x);

    // 2. gated = (x@w_input_proj^T+b) * sigmoid(x@w_in_gate^T+b)
    tf32_dual_gemm<<<dim3(HID / 128, BATCH / 64), 256, SMEMDUAL>>>(
        x, w_input_proj, b_input_proj, w_in_gate, b_in_gate, gated);

    // 3. zxbcdt = gated @ w_in_proj^T
    tf32_gemm<128><<<dim3((DINP + 127) / 128, BATCH / 128), 256, SMEM128>>>(
        gated, w_in_proj, nullptr, nullptr, zx, BATCH, DINP, HID, 0);

    // 4. mega-fused conv + dt + SSM + gate + rmsnorm (writes new_conv + new_ssm + yn)
    ssm_mega<<<BATCH * NG, 512>>>(conv_state, conv_w, conv_b, ssm_state, zx,
                                  A_log, Dp, dt_bias, norm_w,
                                  out_conv, out_ssm, yn);

    // 5. outpre = yn @ w_out_proj^T + gated
    tf32_gemm<64><<<dim3(HID / 128, BATCH / 64), 256, SMEM64>>>(
        yn, w_out_proj, nullptr, gated, outpre, BATCH, HID, DIN, 2);

    // 6. outf = outpre * sigmoid(outpre @ w_out_gate^T + b)
    tf32_gemm<64><<<dim3(HID / 128, BATCH / 64), 256, SMEM64>>>(
        outpre, w_out_gate, b_out_gate, outpre, outf, BATCH, HID, HID, 1);

    // 7. clip = outf @ w_proj^T + b
    tf32_gemm<64><<<dim3(CLIP / 128, BATCH / 64), 256, SMEM64>>>(
        outf, w_proj, b_proj, nullptr, out_clip, BATCH, CLIP, HID, 0);
}